// round 3
// baseline (speedup 1.0000x reference)
#include <cuda_runtime.h>
#include <cstdint>

#define NN 50000
#define NE 500000
#define DD 128

// Scratch (static __device__ arrays: the allowed scratch mechanism)
__device__ float g_Y[(size_t)NN * 1024];    // Y[n][k*128+o] = sum_i x[n,i] W1[i,k,o]      (i in [0,128))
__device__ float g_Z[(size_t)NN * 1024];    // Z[n][k*128+o] = sum_i x[n,i] W1[128+i,k,o]
__device__ float g_agg[(size_t)NN * DD];    // scatter-add aggregation

__device__ __forceinline__ float swishf(float v) {
    return __fdividef(v, 1.0f + __expf(-v));
}

__global__ void k_zero_agg() {
    int i = blockIdx.x * blockDim.x + threadIdx.x;
    const int n = NN * DD;
    for (; i < n; i += gridDim.x * blockDim.x) g_agg[i] = 0.0f;
}

// ---------------------------------------------------------------------------
// Precompute Y and Z:  [50000 x 128] @ [128 x 1024]  (two halves of W1)
// grid: (391 node tiles, 8 col tiles, 2 halves), 256 threads, 128x128 C tile
// ---------------------------------------------------------------------------
__global__ void __launch_bounds__(256) k_precompute(const float* __restrict__ x,
                                                    const float* __restrict__ W1) {
    __shared__ float As[8][132];
    __shared__ float Bs[8][128];
    const int n0 = blockIdx.x * 128;
    const int c0 = blockIdx.y * 128;
    const float* B = W1 + (size_t)blockIdx.z * 128 * 1024 + c0;
    float* C = (blockIdx.z == 0) ? g_Y : g_Z;
    const int tid = threadIdx.x;
    const int tx = tid & 15, ty = tid >> 4;
    const int lr = tid >> 1, lc4 = (tid & 1) * 4;
    const int br = tid >> 5, bc4 = (tid & 31) * 4;
    int gn_l = n0 + lr; if (gn_l >= NN) gn_l = NN - 1;

    float acc[8][8];
#pragma unroll
    for (int m = 0; m < 8; m++)
#pragma unroll
        for (int n = 0; n < 8; n++) acc[m][n] = 0.0f;

    for (int i0 = 0; i0 < 128; i0 += 8) {
        float4 av = *(const float4*)(x + (size_t)gn_l * 128 + i0 + lc4);
        As[lc4 + 0][lr] = av.x;
        As[lc4 + 1][lr] = av.y;
        As[lc4 + 2][lr] = av.z;
        As[lc4 + 3][lr] = av.w;
        *(float4*)&Bs[br][bc4] = *(const float4*)(B + (size_t)(i0 + br) * 1024 + bc4);
        __syncthreads();
#pragma unroll
        for (int kk = 0; kk < 8; kk++) {
            float4 a0 = *(const float4*)&As[kk][ty * 4];
            float4 a1 = *(const float4*)&As[kk][64 + ty * 4];
            float4 b0 = *(const float4*)&Bs[kk][tx * 4];
            float4 b1 = *(const float4*)&Bs[kk][64 + tx * 4];
            float a[8] = {a0.x, a0.y, a0.z, a0.w, a1.x, a1.y, a1.z, a1.w};
            float b[8] = {b0.x, b0.y, b0.z, b0.w, b1.x, b1.y, b1.z, b1.w};
#pragma unroll
            for (int m = 0; m < 8; m++)
#pragma unroll
                for (int n = 0; n < 8; n++) acc[m][n] = fmaf(a[m], b[n], acc[m][n]);
        }
        __syncthreads();
    }
#pragma unroll
    for (int m = 0; m < 8; m++) {
        const int row = (m < 4) ? (ty * 4 + m) : (64 + ty * 4 + m - 4);
        const int gn = n0 + row;
        if (gn >= NN) continue;
        float* cp = C + (size_t)gn * 1024 + c0;
        float4 v0 = {acc[m][0], acc[m][1], acc[m][2], acc[m][3]};
        float4 v1 = {acc[m][4], acc[m][5], acc[m][6], acc[m][7]};
        *(float4*)(cp + tx * 4) = v0;
        *(float4*)(cp + 64 + tx * 4) = v1;
    }
}

// ---------------------------------------------------------------------------
// Edge kernel: 128 edges per CTA, 256 threads.
// phase1: m1 = swish(b1 + sum_k ea_k*(Y[dst]+Z[src]) + amf-term)  -> smem (transposed)
// phase2: C = sum_{k,i} (m1[e,i]*ea[e,k]) * W2[i,k,o]   (K=1024 sgemm)
// phase3: atomicAdd(agg[dst], swish(C + b2))
// ---------------------------------------------------------------------------
__global__ void __launch_bounds__(256, 1) k_edges(
    const int* __restrict__ eidx, const float* __restrict__ ea,
    const float* __restrict__ amf, const float* __restrict__ W1,
    const float* __restrict__ b1, const float* __restrict__ W2,
    const float* __restrict__ b2) {
    extern __shared__ float sm[];
    float* s_ea  = sm;            // 1024 floats: [128 edges][8]
    float* s_w1c = sm + 1024;     // 3072: W1 rows 256..258  [i][k][o]
    float* s_m1T = sm + 4096;     // 128*132: m1 transposed [i][e]
    float* s_Bs  = sm + 20992;    // 8*128 W2 tile
    const int tid = threadIdx.x;
    const int e0 = blockIdx.x * 128;

    for (int i = tid; i < 1024; i += 256) {
        const int idx = e0 * 8 + i;
        s_ea[i] = (idx < NE * 8) ? ea[idx] : 0.0f;
    }
    for (int i = tid; i < 3072; i += 256) s_w1c[i] = W1[256 * 1024 + i];
    __syncthreads();

    // ----- phase 1: 2 threads per edge, 64 outputs each -----
    {
        const int e = tid >> 1;
        const int oh = (tid & 1) * 64;
        const int ge = e0 + e;
        const bool valid = ge < NE;
        const int gsrc = valid ? eidx[ge] : 0;
        const int gdst = valid ? eidx[NE + ge] : 0;
        const float am0 = valid ? amf[ge * 3 + 0] : 0.0f;
        const float am1 = valid ? amf[ge * 3 + 1] : 0.0f;
        const float am2 = valid ? amf[ge * 3 + 2] : 0.0f;
        float acc[64];
#pragma unroll
        for (int j = 0; j < 64; j += 4) {
            float4 bv = *(const float4*)(b1 + oh + j);
            acc[j] = bv.x; acc[j + 1] = bv.y; acc[j + 2] = bv.z; acc[j + 3] = bv.w;
        }
        const float* Yb = g_Y + (size_t)gdst * 1024 + oh;
        const float* Zb = g_Z + (size_t)gsrc * 1024 + oh;
#pragma unroll 1
        for (int k = 0; k < 8; k++) {
            const float eak = s_ea[e * 8 + k];
            const float4* y4 = (const float4*)(Yb + k * 128);
            const float4* z4 = (const float4*)(Zb + k * 128);
            const float4* wA = (const float4*)(s_w1c + k * 128 + oh);
            const float4* wB = (const float4*)(s_w1c + 1024 + k * 128 + oh);
            const float4* wC = (const float4*)(s_w1c + 2048 + k * 128 + oh);
#pragma unroll
            for (int j = 0; j < 16; j++) {
                float4 t = y4[j];
                float4 z = z4[j];
                float4 wa = wA[j], wb = wB[j], wc = wC[j];
                float vx = t.x + z.x, vy = t.y + z.y, vz = t.z + z.z, vw = t.w + z.w;
                vx = fmaf(am0, wa.x, vx); vy = fmaf(am0, wa.y, vy);
                vz = fmaf(am0, wa.z, vz); vw = fmaf(am0, wa.w, vw);
                vx = fmaf(am1, wb.x, vx); vy = fmaf(am1, wb.y, vy);
                vz = fmaf(am1, wb.z, vz); vw = fmaf(am1, wb.w, vw);
                vx = fmaf(am2, wc.x, vx); vy = fmaf(am2, wc.y, vy);
                vz = fmaf(am2, wc.z, vz); vw = fmaf(am2, wc.w, vw);
                acc[4 * j + 0] = fmaf(eak, vx, acc[4 * j + 0]);
                acc[4 * j + 1] = fmaf(eak, vy, acc[4 * j + 1]);
                acc[4 * j + 2] = fmaf(eak, vz, acc[4 * j + 2]);
                acc[4 * j + 3] = fmaf(eak, vw, acc[4 * j + 3]);
            }
        }
#pragma unroll
        for (int j = 0; j < 64; j++)
            s_m1T[(oh + j) * 132 + e] = swishf(acc[j]);
    }
    __syncthreads();

    // ----- phase 2: 128x128 C tile, K = 8k * 128i -----
    const int tx = tid & 15, ty = tid >> 4;
    const int bi = tid >> 5, bo4 = (tid & 31) * 4;
    float c[8][8];
#pragma unroll
    for (int m = 0; m < 8; m++)
#pragma unroll
        for (int n = 0; n < 8; n++) c[m][n] = 0.0f;

    for (int k = 0; k < 8; k++) {
        float eas[8];
#pragma unroll
        for (int m = 0; m < 8; m++) {
            const int row = (m < 4) ? (ty * 4 + m) : (64 + ty * 4 + m - 4);
            eas[m] = s_ea[row * 8 + k];
        }
        for (int i0 = 0; i0 < 128; i0 += 8) {
            __syncthreads();
            *(float4*)&s_Bs[bi * 128 + bo4] =
                *(const float4*)(W2 + ((size_t)(i0 + bi) * 8 + k) * 128 + bo4);
            __syncthreads();
#pragma unroll
            for (int kk = 0; kk < 8; kk++) {
                const float* ar = s_m1T + (i0 + kk) * 132;
                float4 a0 = *(const float4*)(ar + ty * 4);
                float4 a1 = *(const float4*)(ar + 64 + ty * 4);
                float4 b0 = *(const float4*)(s_Bs + kk * 128 + tx * 4);
                float4 b1v = *(const float4*)(s_Bs + kk * 128 + 64 + tx * 4);
                float a[8] = {a0.x * eas[0], a0.y * eas[1], a0.z * eas[2], a0.w * eas[3],
                              a1.x * eas[4], a1.y * eas[5], a1.z * eas[6], a1.w * eas[7]};
                float b[8] = {b0.x, b0.y, b0.z, b0.w, b1v.x, b1v.y, b1v.z, b1v.w};
#pragma unroll
                for (int m = 0; m < 8; m++)
#pragma unroll
                    for (int n = 0; n < 8; n++) c[m][n] = fmaf(a[m], b[n], c[m][n]);
            }
        }
    }

    // ----- phase 3: swish + scatter-add -----
    float4 b2lo = *(const float4*)(b2 + tx * 4);
    float4 b2hi = *(const float4*)(b2 + 64 + tx * 4);
    const float bb[8] = {b2lo.x, b2lo.y, b2lo.z, b2lo.w, b2hi.x, b2hi.y, b2hi.z, b2hi.w};
#pragma unroll
    for (int m = 0; m < 8; m++) {
        const int row = (m < 4) ? (ty * 4 + m) : (64 + ty * 4 + m - 4);
        const int ge = e0 + row;
        if (ge >= NE) continue;
        const int gd = eidx[NE + ge];
        float* ap = g_agg + (size_t)gd * 128;
#pragma unroll
        for (int n = 0; n < 8; n++) {
            const int col = (n < 4) ? (tx * 4 + n) : (64 + tx * 4 + n - 4);
            atomicAdd(ap + col, swishf(c[m][n] + bb[n]));
        }
    }
}

// ---------------------------------------------------------------------------
// Node kernel: 128 nodes per CTA. Layer3 (K = 259*8) then Layer4 (K = 128*8).
// ---------------------------------------------------------------------------
__global__ void __launch_bounds__(256, 1) k_nodes(
    const float* __restrict__ x, const float* __restrict__ na,
    const float* __restrict__ anf,
    const float* __restrict__ W3, const float* __restrict__ b3,
    const float* __restrict__ W4, const float* __restrict__ b4,
    float* __restrict__ out) {
    extern __shared__ float sm[];
    float* s_na   = sm;            // 1024
    float* s_anfT = sm + 1024;     // 8*132 (rows 3..7 zero)
    float* s_xT   = sm + 2080;     // 128*132   (reused as uT for layer 4)
    float* s_gT   = sm + 18976;    // 128*132
    float* s_Bs   = sm + 35872;    // 1024
    const int tid = threadIdx.x;
    const int n0 = blockIdx.x * 128;
    const int tx = tid & 15, ty = tid >> 4;
    const int bi = tid >> 5, bo4 = (tid & 31) * 4;

    for (int i = tid; i < 1024; i += 256) {
        const int idx = n0 * 8 + i;
        s_na[i] = (idx < NN * 8) ? na[idx] : 0.0f;
    }
    {
        const int r = tid >> 1;
        const int off = (tid & 1) * 64;
        int gn = n0 + r; if (gn >= NN) gn = NN - 1;
#pragma unroll
        for (int j = 0; j < 64; j += 4) {
            float4 v = *(const float4*)(x + (size_t)gn * 128 + off + j);
            s_xT[(off + j + 0) * 132 + r] = v.x;
            s_xT[(off + j + 1) * 132 + r] = v.y;
            s_xT[(off + j + 2) * 132 + r] = v.z;
            s_xT[(off + j + 3) * 132 + r] = v.w;
            float4 g = *(const float4*)(g_agg + (size_t)gn * 128 + off + j);
            s_gT[(off + j + 0) * 132 + r] = g.x;
            s_gT[(off + j + 1) * 132 + r] = g.y;
            s_gT[(off + j + 2) * 132 + r] = g.z;
            s_gT[(off + j + 3) * 132 + r] = g.w;
        }
    }
    if (tid < 128) {
        int gn = n0 + tid;
        const bool v = gn < NN;
        if (!v) gn = 0;
#pragma unroll
        for (int i = 0; i < 8; i++)
            s_anfT[i * 132 + tid] = (i < 3 && v) ? anf[gn * 3 + i] : 0.0f;
    }
    __syncthreads();

    float c[8][8];
#pragma unroll
    for (int m = 0; m < 8; m++)
#pragma unroll
        for (int n = 0; n < 8; n++) c[m][n] = 0.0f;

    // ----- layer 3: K = 259*8 -----
    for (int k = 0; k < 8; k++) {
        float nas[8];
#pragma unroll
        for (int m = 0; m < 8; m++) {
            const int row = (m < 4) ? (ty * 4 + m) : (64 + ty * 4 + m - 4);
            nas[m] = s_na[row * 8 + k];
        }
        for (int blk = 0; blk < 33; blk++) {
            const float* AT = (blk < 16) ? (s_xT + blk * 8 * 132)
                            : (blk < 32) ? (s_gT + (blk - 16) * 8 * 132)
                                         : s_anfT;
            const int gi = blk * 8 + bi;
            __syncthreads();
            float4 bv = make_float4(0.f, 0.f, 0.f, 0.f);
            if (gi < 259)
                bv = *(const float4*)(W3 + ((size_t)gi * 8 + k) * 128 + bo4);
            *(float4*)&s_Bs[bi * 128 + bo4] = bv;
            __syncthreads();
#pragma unroll
            for (int kk = 0; kk < 8; kk++) {
                const float* ar = AT + kk * 132;
                float4 a0 = *(const float4*)(ar + ty * 4);
                float4 a1 = *(const float4*)(ar + 64 + ty * 4);
                float4 b0 = *(const float4*)(s_Bs + kk * 128 + tx * 4);
                float4 b1v = *(const float4*)(s_Bs + kk * 128 + 64 + tx * 4);
                float a[8] = {a0.x * nas[0], a0.y * nas[1], a0.z * nas[2], a0.w * nas[3],
                              a1.x * nas[4], a1.y * nas[5], a1.z * nas[6], a1.w * nas[7]};
                float b[8] = {b0.x, b0.y, b0.z, b0.w, b1v.x, b1v.y, b1v.z, b1v.w};
#pragma unroll
                for (int m = 0; m < 8; m++)
#pragma unroll
                    for (int n = 0; n < 8; n++) c[m][n] = fmaf(a[m], b[n], c[m][n]);
            }
        }
    }

    // u = swish(c + b3) -> uT (overwrite s_xT; all layer-3 reads are done)
    __syncthreads();
    {
        float4 b3lo = *(const float4*)(b3 + tx * 4);
        float4 b3hi = *(const float4*)(b3 + 64 + tx * 4);
        const float bb[8] = {b3lo.x, b3lo.y, b3lo.z, b3lo.w, b3hi.x, b3hi.y, b3hi.z, b3hi.w};
#pragma unroll
        for (int m = 0; m < 8; m++) {
            const int row = (m < 4) ? (ty * 4 + m) : (64 + ty * 4 + m - 4);
#pragma unroll
            for (int n = 0; n < 8; n++) {
                const int col = (n < 4) ? (tx * 4 + n) : (64 + tx * 4 + n - 4);
                s_xT[col * 132 + row] = swishf(c[m][n] + bb[n]);
            }
        }
    }
    __syncthreads();

    // ----- layer 4: K = 128*8 -----
#pragma unroll
    for (int m = 0; m < 8; m++)
#pragma unroll
        for (int n = 0; n < 8; n++) c[m][n] = 0.0f;

    for (int k = 0; k < 8; k++) {
        float nas[8];
#pragma unroll
        for (int m = 0; m < 8; m++) {
            const int row = (m < 4) ? (ty * 4 + m) : (64 + ty * 4 + m - 4);
            nas[m] = s_na[row * 8 + k];
        }
        for (int i0 = 0; i0 < 128; i0 += 8) {
            __syncthreads();
            *(float4*)&s_Bs[bi * 128 + bo4] =
                *(const float4*)(W4 + ((size_t)(i0 + bi) * 8 + k) * 128 + bo4);
            __syncthreads();
#pragma unroll
            for (int kk = 0; kk < 8; kk++) {
                const float* ar = s_xT + (i0 + kk) * 132;
                float4 a0 = *(const float4*)(ar + ty * 4);
                float4 a1 = *(const float4*)(ar + 64 + ty * 4);
                float4 b0 = *(const float4*)(s_Bs + kk * 128 + tx * 4);
                float4 b1v = *(const float4*)(s_Bs + kk * 128 + 64 + tx * 4);
                float a[8] = {a0.x * nas[0], a0.y * nas[1], a0.z * nas[2], a0.w * nas[3],
                              a1.x * nas[4], a1.y * nas[5], a1.z * nas[6], a1.w * nas[7]};
                float b[8] = {b0.x, b0.y, b0.z, b0.w, b1v.x, b1v.y, b1v.z, b1v.w};
#pragma unroll
                for (int m = 0; m < 8; m++)
#pragma unroll
                    for (int n = 0; n < 8; n++) c[m][n] = fmaf(a[m], b[n], c[m][n]);
            }
        }
    }

    // out = c + b4
    {
        float4 b4lo = *(const float4*)(b4 + tx * 4);
        float4 b4hi = *(const float4*)(b4 + 64 + tx * 4);
#pragma unroll
        for (int m = 0; m < 8; m++) {
            const int row = (m < 4) ? (ty * 4 + m) : (64 + ty * 4 + m - 4);
            const int gn = n0 + row;
            if (gn >= NN) continue;
            float4 v0 = {c[m][0] + b4lo.x, c[m][1] + b4lo.y, c[m][2] + b4lo.z, c[m][3] + b4lo.w};
            float4 v1 = {c[m][4] + b4hi.x, c[m][5] + b4hi.y, c[m][6] + b4hi.z, c[m][7] + b4hi.w};
            *(float4*)(out + (size_t)gn * 128 + tx * 4) = v0;
            *(float4*)(out + (size_t)gn * 128 + 64 + tx * 4) = v1;
        }
    }
}

extern "C" void kernel_launch(void* const* d_in, const int* in_sizes, int n_in,
                              void* d_out, int out_size) {
    const float *x = nullptr, *ea = nullptr, *na = nullptr, *amf = nullptr, *anf = nullptr;
    const float *W1 = nullptr, *b1 = nullptr, *W2 = nullptr, *b2 = nullptr;
    const float *W3 = nullptr, *b3 = nullptr, *W4 = nullptr, *b4 = nullptr;
    const int* eidx = nullptr;
    for (int i = 0; i < n_in; i++) {
        switch (in_sizes[i]) {
            case 6400000: x   = (const float*)d_in[i]; break;
            case 1000000: eidx = (const int*)d_in[i]; break;
            case 4000000: ea  = (const float*)d_in[i]; break;
            case 400000:  na  = (const float*)d_in[i]; break;
            case 1500000: amf = (const float*)d_in[i]; break;
            case 150000:  anf = (const float*)d_in[i]; break;
            case 265216:  if (!W1) W1 = (const float*)d_in[i]; else W3 = (const float*)d_in[i]; break;
            case 131072:  if (!W2) W2 = (const float*)d_in[i]; else W4 = (const float*)d_in[i]; break;
            case 128:
                if (!b1) b1 = (const float*)d_in[i];
                else if (!b2) b2 = (const float*)d_in[i];
                else if (!b3) b3 = (const float*)d_in[i];
                else b4 = (const float*)d_in[i];
                break;
            default: break;  // batch (50000 int64) unused
        }
    }

    cudaFuncSetAttribute(k_edges, cudaFuncAttributeMaxDynamicSharedMemorySize, 88064);
    cudaFuncSetAttribute(k_nodes, cudaFuncAttributeMaxDynamicSharedMemorySize, 147584);

    k_zero_agg<<<12500, 512>>>();
    dim3 gp(391, 8, 2);
    k_precompute<<<gp, 256>>>(x, W1);
    k_edges<<<3907, 256, 88064>>>(eidx, ea, amf, W1, b1, W2, b2);
    k_nodes<<<391, 256, 147584>>>(x, na, anf, W3, b3, W4, b4, (float*)d_out);
}

// round 6
// speedup vs baseline: 3.0211x; 3.0211x over previous
#include <cuda_runtime.h>
#include <cuda_fp16.h>
#include <mma.h>
#include <cstdint>
using namespace nvcuda;

#define NN 50000
#define NE 500000
#define LDA 136
#define LDC 132

__device__ float g_agg[(size_t)NN * 128];
// fp16 weight images [grp][k][o*128+i]; grp: 0=W1(x_i) 1=W1(x_j) 2=W2 3=W3(x) 4=W3(agg) 5=W4
__device__ __align__(16) __half g_W16[6][8][16384];

__device__ __forceinline__ float swishf(float v) { return __fdividef(v, 1.0f + __expf(-v)); }

__global__ void k_zero() {
    int i = blockIdx.x * blockDim.x + threadIdx.x;
    for (; i < NN * 128; i += gridDim.x * blockDim.x) g_agg[i] = 0.0f;
}

__global__ void k_prep(const float* __restrict__ W1, const float* __restrict__ W2,
                       const float* __restrict__ W3, const float* __restrict__ W4) {
    const int grp = blockIdx.x >> 3, k = blockIdx.x & 7;
    const float* W; int ioff = 0;
    switch (grp) {
        case 0: W = W1; break;
        case 1: W = W1; ioff = 128; break;
        case 2: W = W2; break;
        case 3: W = W3; break;
        case 4: W = W3; ioff = 128; break;
        default: W = W4; break;
    }
    for (int idx = threadIdx.x; idx < 16384; idx += blockDim.x) {
        const int o = idx >> 7, i = idx & 127;
        g_W16[grp][k][idx] = __float2half_rn(W[(size_t)(ioff + i) * 1024 + k * 128 + o]);
    }
}

// smem byte offsets
#define OFF_ATTR 0
#define OFF_EXT  4096
#define OFF_IDX  5632
#define OFF_BIAS 6656
#define OFF_WC   7680
#define OFF_A0   20480
#define OFF_A1   55296
#define OFF_B0   90112
#define OFF_B1   124928
#define OFF_C    159744
#define SMEM_SZ  227328

// MODE 0: edges (rows=edges, gather x[dst]/x[src], scatter to g_agg)
// MODE 1: nodes (rows=nodes, x then g_agg, store out)
template <int MODE>
__global__ void __launch_bounds__(256, 1) k_main(
    const int* __restrict__ eidx, const float* __restrict__ attr,
    const float* __restrict__ ext, const float* __restrict__ x,
    const float* __restrict__ wcs, const float* __restrict__ bA,
    const float* __restrict__ bB, float* __restrict__ outp)
{
    extern __shared__ unsigned char sm[];
    float* s_attr = (float*)sm;
    float* s_ext  = (float*)(sm + OFF_EXT);
    int*   s_idx  = (int*)(sm + OFF_IDX);
    float* s_bias = (float*)(sm + OFF_BIAS);
    float* s_wc   = (float*)(sm + OFF_WC);
    __half* sA[2] = {(__half*)(sm + OFF_A0), (__half*)(sm + OFF_A1)};
    const __half* sB[2] = {(const __half*)(sm + OFF_B0), (const __half*)(sm + OFF_B1)};
    float* sC = (float*)(sm + OFF_C);
    uint32_t sbB[2];
    asm("{ .reg .u64 t; cvta.to.shared.u64 t, %1; cvt.u32.u64 %0, t; }" : "=r"(sbB[0]) : "l"(sm + OFF_B0));
    asm("{ .reg .u64 t; cvta.to.shared.u64 t, %1; cvt.u32.u64 %0, t; }" : "=r"(sbB[1]) : "l"(sm + OFF_B1));

    const int tid = threadIdx.x, wid = tid >> 5;
    const int r = tid >> 1, c0 = (tid & 1) * 64;
    const int t0 = blockIdx.x * 128;
    const int NROW = MODE ? NN : NE;
    const int wg0 = MODE ? 3 : 0;
    const int wr = (wid & 3) * 32, wc = (wid >> 2) * 64;

    for (int i = tid; i < 1024; i += 256) { int gi = t0 * 8 + i; s_attr[i] = (gi < NROW * 8) ? attr[gi] : 0.f; }
    for (int i = tid; i < 384; i += 256)  { int gi = t0 * 3 + i; s_ext[i]  = (gi < NROW * 3) ? ext[gi]  : 0.f; }
    if (tid < 128) {
        s_bias[tid] = bA[tid]; s_bias[128 + tid] = bB[tid];
        if (!MODE) {
            const int e = t0 + tid;
            s_idx[tid]       = (e < NE) ? eidx[e]      : 0;   // src
            s_idx[128 + tid] = (e < NE) ? eidx[NE + e] : 0;   // dst
        }
    }
    for (int i = tid; i < 3072; i += 256) s_wc[i] = wcs[i];
    __syncthreads();

    int rowA;
    if (MODE) { const int gn = t0 + r; rowA = (gn < NN) ? gn : NN - 1; }
    else rowA = s_idx[128 + r];

    float rrow[64];
    {
        const float4* p = (const float4*)(x + (size_t)rowA * 128 + c0);
#pragma unroll
        for (int j = 0; j < 16; j++) {
            float4 v = p[j];
            rrow[4*j] = v.x; rrow[4*j+1] = v.y; rrow[4*j+2] = v.z; rrow[4*j+3] = v.w;
        }
    }

    // prefetch B(0)
    {
        const char* src = (const char*)g_W16[wg0][0];
#pragma unroll
        for (int it = 0; it < 8; it++) {
            const int idx = tid + it * 256, o = idx >> 4, c = idx & 15;
            asm volatile("cp.async.cg.shared.global [%0], [%1], 16;"
                         :: "r"(sbB[0] + (uint32_t)(o * 272 + c * 16)), "l"(src + o * 256 + c * 16));
        }
        asm volatile("cp.async.commit_group;" ::: "memory");
    }

    wmma::fragment<wmma::accumulator, 16, 16, 16, float> acc[2][4];
#pragma unroll
    for (int m = 0; m < 2; m++)
#pragma unroll
        for (int n = 0; n < 4; n++) wmma::fill_fragment(acc[m][n], 0.f);

#pragma unroll 1
    for (int g = 0; g < 24; g++) {
        if (g == 8) {  // switch row source: x[src] (edges) / g_agg (nodes)
            const float* base = MODE ? ((const float*)g_agg + (size_t)rowA * 128)
                                     : (x + (size_t)s_idx[r] * 128);
            const float4* p = (const float4*)(base + c0);
#pragma unroll
            for (int j = 0; j < 16; j++) {
                float4 v = p[j];
                rrow[4*j] = v.x; rrow[4*j+1] = v.y; rrow[4*j+2] = v.z; rrow[4*j+3] = v.w;
            }
        }
        if (g == 16) {  // epilogue 1: rows = swish(C + bA + ext-rows term)
#pragma unroll
            for (int m = 0; m < 2; m++)
#pragma unroll
                for (int n = 0; n < 4; n++)
                    wmma::store_matrix_sync(sC + (wr + 16*m) * LDC + wc + 16*n, acc[m][n], LDC, wmma::mem_row_major);
            __syncthreads();
            float p24[24];
#pragma unroll
            for (int i = 0; i < 3; i++)
#pragma unroll
                for (int k2 = 0; k2 < 8; k2++) p24[i * 8 + k2] = s_ext[r * 3 + i] * s_attr[r * 8 + k2];
#pragma unroll
            for (int j4 = 0; j4 < 16; j4++) {
                float4 t = *(float4*)(sC + r * LDC + c0 + j4 * 4);
#pragma unroll
                for (int q = 0; q < 24; q++) {
                    float4 wv = *(const float4*)(s_wc + q * 128 + c0 + j4 * 4);
                    t.x = fmaf(p24[q], wv.x, t.x); t.y = fmaf(p24[q], wv.y, t.y);
                    t.z = fmaf(p24[q], wv.z, t.z); t.w = fmaf(p24[q], wv.w, t.w);
                }
                float4 bv = *(const float4*)(s_bias + c0 + j4 * 4);
                rrow[4*j4]   = swishf(t.x + bv.x); rrow[4*j4+1] = swishf(t.y + bv.y);
                rrow[4*j4+2] = swishf(t.z + bv.z); rrow[4*j4+3] = swishf(t.w + bv.w);
            }
#pragma unroll
            for (int m = 0; m < 2; m++)
#pragma unroll
                for (int n = 0; n < 4; n++) wmma::fill_fragment(acc[m][n], 0.f);
            __syncthreads();
        }
        // build A(g) = attr_k * rrow  (fp16)
        {
            const float sc = s_attr[r * 8 + (g & 7)];
            __half2* dst = (__half2*)(sA[g & 1] + r * LDA + c0);
#pragma unroll
            for (int j = 0; j < 32; j++)
                dst[j] = __floats2half2_rn(rrow[2*j] * sc, rrow[2*j+1] * sc);
        }
        asm volatile("cp.async.wait_group 0;" ::: "memory");
        __syncthreads();
        if (g < 23) {  // prefetch B(g+1)
            const int ng = g + 1;
            const char* src = (const char*)g_W16[wg0 + (ng >> 3)][ng & 7];
            const uint32_t db = sbB[ng & 1];
#pragma unroll
            for (int it = 0; it < 8; it++) {
                const int idx = tid + it * 256, o = idx >> 4, c = idx & 15;
                asm volatile("cp.async.cg.shared.global [%0], [%1], 16;"
                             :: "r"(db + (uint32_t)(o * 272 + c * 16)), "l"(src + o * 256 + c * 16));
            }
            asm volatile("cp.async.commit_group;" ::: "memory");
        }
        // mma over 8 k-steps
        {
            const __half* Ab = sA[g & 1];
            const __half* Bb = sB[g & 1];
#pragma unroll
            for (int ks = 0; ks < 8; ks++) {
                wmma::fragment<wmma::matrix_a, 16, 16, 16, __half, wmma::row_major> fa0, fa1;
                wmma::load_matrix_sync(fa0, Ab + (size_t)wr * LDA + ks * 16, LDA);
                wmma::load_matrix_sync(fa1, Ab + (size_t)(wr + 16) * LDA + ks * 16, LDA);
#pragma unroll
                for (int n = 0; n < 4; n++) {
                    wmma::fragment<wmma::matrix_b, 16, 16, 16, __half, wmma::col_major> fb;
                    wmma::load_matrix_sync(fb, Bb + (size_t)(wc + 16 * n) * LDA + ks * 16, LDA);
                    wmma::mma_sync(acc[0][n], fa0, fb, acc[0][n]);
                    wmma::mma_sync(acc[1][n], fa1, fb, acc[1][n]);
                }
            }
        }
    }

    // final epilogue
#pragma unroll
    for (int m = 0; m < 2; m++)
#pragma unroll
        for (int n = 0; n < 4; n++)
            wmma::store_matrix_sync(sC + (wr + 16*m) * LDC + wc + 16*n, acc[m][n], LDC, wmma::mem_row_major);
    __syncthreads();
    if (t0 + r < NROW) {
        if (MODE) {
            float* op = outp + (size_t)(t0 + r) * 128 + c0;
#pragma unroll
            for (int j4 = 0; j4 < 16; j4++) {
                float4 t = *(float4*)(sC + r * LDC + c0 + j4 * 4);
                float4 bv = *(const float4*)(s_bias + 128 + c0 + j4 * 4);
                *(float4*)(op + j4 * 4) = make_float4(t.x + bv.x, t.y + bv.y, t.z + bv.z, t.w + bv.w);
            }
        } else {
            float* ap = g_agg + (size_t)rowA * 128 + c0;
#pragma unroll
            for (int j4 = 0; j4 < 16; j4++) {
                float4 t = *(float4*)(sC + r * LDC + c0 + j4 * 4);
                float4 bv = *(const float4*)(s_bias + 128 + c0 + j4 * 4);
                float vx = swishf(t.x + bv.x), vy = swishf(t.y + bv.y);
                float vz = swishf(t.z + bv.z), vw = swishf(t.w + bv.w);
                asm volatile("red.global.add.v4.f32 [%0], {%1, %2, %3, %4};"
                             :: "l"(ap + j4 * 4), "f"(vx), "f"(vy), "f"(vz), "f"(vw)
                             : "memory");
            }
        }
    }
}

extern "C" void kernel_launch(void* const* d_in, const int* in_sizes, int n_in,
                              void* d_out, int out_size) {
    const float *x = nullptr, *ea = nullptr, *na = nullptr, *amf = nullptr, *anf = nullptr;
    const float *W1 = nullptr, *b1 = nullptr, *W2 = nullptr, *b2 = nullptr;
    const float *W3 = nullptr, *b3 = nullptr, *W4 = nullptr, *b4 = nullptr;
    const int* eidx = nullptr;
    for (int i = 0; i < n_in; i++) {
        switch (in_sizes[i]) {
            case 6400000: x   = (const float*)d_in[i]; break;
            case 1000000: eidx = (const int*)d_in[i]; break;
            case 4000000: ea  = (const float*)d_in[i]; break;
            case 400000:  na  = (const float*)d_in[i]; break;
            case 1500000: amf = (const float*)d_in[i]; break;
            case 150000:  anf = (const float*)d_in[i]; break;
            case 265216:  if (!W1) W1 = (const float*)d_in[i]; else W3 = (const float*)d_in[i]; break;
            case 131072:  if (!W2) W2 = (const float*)d_in[i]; else W4 = (const float*)d_in[i]; break;
            case 128:
                if (!b1) b1 = (const float*)d_in[i];
                else if (!b2) b2 = (const float*)d_in[i];
                else if (!b3) b3 = (const float*)d_in[i];
                else b4 = (const float*)d_in[i];
                break;
            default: break;
        }
    }

    cudaFuncSetAttribute(k_main<0>, cudaFuncAttributeMaxDynamicSharedMemorySize, SMEM_SZ);
    cudaFuncSetAttribute(k_main<1>, cudaFuncAttributeMaxDynamicSharedMemorySize, SMEM_SZ);

    k_prep<<<48, 256>>>(W1, W2, W3, W4);
    k_zero<<<6400, 512>>>();
    k_main<0><<<3907, 256, SMEM_SZ>>>(eidx, ea, amf, x, W1 + 256 * 1024, b1, b2, nullptr);
    k_main<1><<<391, 256, SMEM_SZ>>>(eidx, na, anf, x, W3 + 256 * 1024, b3, b4, (float*)d_out);
}